// round 2
// baseline (speedup 1.0000x reference)
#include <cuda_runtime.h>
#include <cuda_bf16.h>

// BCE_for_non_zero: mean over [B,14] of BCE-with-logits * per-row group mask.
//
// d_in[0] = inputs  float32 [B*14]
// d_in[1] = targets float32 [B*14]
// d_in[2] = groups  int32   [14]   (values in {0,1,2,3}; group 0 always kept)
// d_out   = float32 [1]
//
// HBM-bound streaming reduction (224 MB in, 4 B out). Strategy: coalesced
// cp.async staging into smem (avoids the 112B-stride L1tex wavefront blowup
// of direct per-row LDGs), then per-thread row compute from smem.

#define C 14
#define TILE_ROWS 256
#define THREADS 256
#define TILE_FLOATS (TILE_ROWS * C)     // 3584
#define TILE_CHUNKS (TILE_FLOATS / 4)   // 896 16B chunks per array

__device__ double g_acc;

__global__ void init_acc_kernel() { g_acc = 0.0; }

__device__ __forceinline__ unsigned smem_u32(const void* p) {
    return (unsigned)__cvta_generic_to_shared(p);
}

__global__ void __launch_bounds__(THREADS) bce_main_kernel(
    const float* __restrict__ x,
    const float* __restrict__ t,
    const int* __restrict__ groups,
    int B)
{
    __shared__ float sx[TILE_FLOATS];
    __shared__ float st[TILE_FLOATS];
    __shared__ int sg[C];

    if (threadIdx.x < C) sg[threadIdx.x] = groups[threadIdx.x];

    const long long row0 = (long long)blockIdx.x * TILE_ROWS;
    long long remain = (long long)B - row0;
    const int rows = (remain < TILE_ROWS) ? (int)remain : TILE_ROWS;
    const int validBytes = rows * (C * 4);
    const int fullChunks = validBytes >> 4;       // 16B chunks fully in-bounds
    const int fullFloats = fullChunks << 2;

    const float* gx = x + row0 * C;
    const float* gt = t + row0 * C;

    const unsigned sxa = smem_u32(sx);
    const unsigned sta = smem_u32(st);

    // Coalesced staging: combined chunk space [0, 2*TILE_CHUNKS).
    // i = tid + k*256 for k=0..6 covers exactly 1792 chunks.
#pragma unroll
    for (int k = 0; k < 7; k++) {
        int i = threadIdx.x + k * THREADS;
        if (i < TILE_CHUNKS) {
            if (i < fullChunks)
                asm volatile("cp.async.cg.shared.global [%0], [%1], 16;"
                             :: "r"(sxa + i * 16), "l"(gx + i * 4));
        } else {
            int j = i - TILE_CHUNKS;
            if (j < fullChunks)
                asm volatile("cp.async.cg.shared.global [%0], [%1], 16;"
                             :: "r"(sta + j * 16), "l"(gt + j * 4));
        }
    }
    asm volatile("cp.async.commit_group;");
    asm volatile("cp.async.wait_group 0;");
    __syncthreads();

    int gl[C];
#pragma unroll
    for (int c = 0; c < C; c++) gl[c] = sg[c];

    float s = 0.0f;
    const int r = threadIdx.x;
    if (r < rows) {
        const int base = r * C;
        float vx[C], vt[C];

        if (base + C <= fullFloats) {
            // common case: whole row staged in smem
#pragma unroll
            for (int c = 0; c < C; c++) { vx[c] = sx[base + c]; vt[c] = st[base + c]; }
        } else {
            // only possible for the last row of an odd-rows tail tile
#pragma unroll
            for (int c = 0; c < C; c++) {
                int idx = base + c;
                if (idx < fullFloats) { vx[c] = sx[idx]; vt[c] = st[idx]; }
                else                  { vx[c] = __ldg(&gx[idx]); vt[c] = __ldg(&gt[idx]); }
            }
        }

        // per-row target sums for groups 1..3 (group 0 always kept)
        float g1 = 0.0f, g2 = 0.0f, g3 = 0.0f;
#pragma unroll
        for (int c = 0; c < C; c++) {
            int g = gl[c];
            float tv = vt[c];
            g1 += (g == 1) ? tv : 0.0f;
            g2 += (g == 2) ? tv : 0.0f;
            g3 += (g == 3) ? tv : 0.0f;
        }
        const float m1 = (g1 > 0.0f) ? 1.0f : 0.0f;
        const float m2 = (g2 > 0.0f) ? 1.0f : 0.0f;
        const float m3 = (g3 > 0.0f) ? 1.0f : 0.0f;

#pragma unroll
        for (int c = 0; c < C; c++) {
            float xv = vx[c];
            float tv = vt[c];
            float ax = fabsf(xv);
            // log1p(exp(-|x|)) with fast intrinsics: when 1+e rounds away the
            // term (|x|>16.6) the dropped part is <1e-7 vs bce ~ 16: negligible
            // at the 1e-3 rel tolerance on the mean.
            float l = __logf(1.0f + __expf(-ax));
            float bce = fmaxf(xv, 0.0f) - xv * tv + l;
            int g = gl[c];
            float m = (g == 0) ? 1.0f
                    : (g == 1) ? m1
                    : (g == 2) ? m2
                    : m3;
            s += bce * m;
        }
    }

    // block reduction
#pragma unroll
    for (int off = 16; off > 0; off >>= 1)
        s += __shfl_down_sync(0xFFFFFFFFu, s, off);

    __shared__ float warp_sums[THREADS / 32];
    const int lane = threadIdx.x & 31;
    const int wid  = threadIdx.x >> 5;
    if (lane == 0) warp_sums[wid] = s;
    __syncthreads();

    if (wid == 0) {
        float v = (lane < (THREADS >> 5)) ? warp_sums[lane] : 0.0f;
#pragma unroll
        for (int off = 4; off > 0; off >>= 1)
            v += __shfl_down_sync(0xFFFFFFFFu, v, off);
        if (lane == 0)
            atomicAdd(&g_acc, (double)v);
    }
}

__global__ void finalize_kernel(float* __restrict__ out, double inv_n) {
    out[0] = (float)(g_acc * inv_n);
}

extern "C" void kernel_launch(void* const* d_in, const int* in_sizes, int n_in,
                              void* d_out, int out_size)
{
    const float* x      = (const float*)d_in[0];
    const float* t      = (const float*)d_in[1];
    const int*   groups = (const int*)d_in[2];
    float* out = (float*)d_out;

    const long long total = in_sizes[0];   // B * C
    const int B = (int)(total / C);

    long long blocksLL = ((long long)B + TILE_ROWS - 1) / TILE_ROWS;
    if (blocksLL < 1) blocksLL = 1;
    const int blocks = (int)blocksLL;

    init_acc_kernel<<<1, 1>>>();
    bce_main_kernel<<<blocks, THREADS>>>(x, t, groups, B);
    finalize_kernel<<<1, 1>>>(out, 1.0 / (double)((long long)B * C));
}

// round 3
// speedup vs baseline: 1.1019x; 1.1019x over previous
#include <cuda_runtime.h>
#include <cuda_bf16.h>

// BCE_for_non_zero: mean over [B,14] of BCE-with-logits * per-row group mask.
//
// d_in[0] = inputs  float32 [B*14]
// d_in[1] = targets float32 [B*14]
// d_in[2] = groups  int32   [14]   (values in {0,1,2,3}; group 0 always kept)
// d_out   = float32 [1]
//
// Single persistent kernel: double-buffered cp.async staging (coalesced 16B
// chunks -> smem), per-thread row compute, block reduce, device-wide atomic
// accumulate, last-block finalize (writes out, resets accumulators so the
// captured graph is replay-deterministic).

#define C 14
#define TILE_ROWS 128
#define THREADS 128
#define STAGE_FLOATS (TILE_ROWS * C)      // 1792
#define STAGE_CHUNKS (STAGE_FLOATS / 4)   // 448 16B chunks per array per stage
#define GRID_CTAS 1036                     // 148 SMs x 7 resident CTAs

__device__ double g_acc;          // zero-init at load; reset by finalize path
__device__ unsigned int g_count;  // ditto

__device__ __forceinline__ unsigned smem_u32(const void* p) {
    return (unsigned)__cvta_generic_to_shared(p);
}

__device__ __forceinline__ void stage_tile(
    const float* __restrict__ gx, const float* __restrict__ gt,
    unsigned sxa, unsigned sta, int fullChunks)
{
#pragma unroll
    for (int k = 0; k < 7; k++) {
        int i = threadIdx.x + k * THREADS;        // 0 .. 895
        if (i < STAGE_CHUNKS) {
            if (i < fullChunks)
                asm volatile("cp.async.cg.shared.global [%0], [%1], 16;"
                             :: "r"(sxa + i * 16), "l"(gx + i * 4));
        } else {
            int j = i - STAGE_CHUNKS;
            if (j < fullChunks)
                asm volatile("cp.async.cg.shared.global [%0], [%1], 16;"
                             :: "r"(sta + j * 16), "l"(gt + j * 4));
        }
    }
}

__global__ void __launch_bounds__(THREADS) bce_fused_kernel(
    const float* __restrict__ x,
    const float* __restrict__ t,
    const int* __restrict__ groups,
    float* __restrict__ out,
    int B, double inv_n)
{
    __shared__ float sx[2][STAGE_FLOATS];
    __shared__ float st[2][STAGE_FLOATS];
    __shared__ int sg[C];
    __shared__ float warp_sums[THREADS / 32];

    if (threadIdx.x < C) sg[threadIdx.x] = groups[threadIdx.x];
    __syncthreads();

    int gl[C];
#pragma unroll
    for (int c = 0; c < C; c++) gl[c] = sg[c];

    const long long nTiles = ((long long)B + TILE_ROWS - 1) / TILE_ROWS;
    const long long G = gridDim.x;

    const unsigned sxa0 = smem_u32(sx[0]);
    const unsigned sta0 = smem_u32(st[0]);
    const unsigned sxa1 = smem_u32(sx[1]);
    const unsigned sta1 = smem_u32(st[1]);

    auto tileRows = [&](long long tile) -> int {
        long long rem = (long long)B - tile * TILE_ROWS;
        return (rem < TILE_ROWS) ? (int)rem : TILE_ROWS;
    };
    auto tileChunks = [&](int rows) -> int {
        return (rows * (C * 4)) >> 4;            // floor(rows*56 / 16)
    };

    float s = 0.0f;
    const long long t0 = blockIdx.x;

    // prologue prefetch
    if (t0 < nTiles) {
        int rows = tileRows(t0);
        stage_tile(x + t0 * STAGE_FLOATS, t + t0 * STAGE_FLOATS,
                   sxa0, sta0, tileChunks(rows));
    }
    asm volatile("cp.async.commit_group;");

    int buf = 0;
    for (long long tile = t0; tile < nTiles; tile += G) {
        const long long tn = tile + G;
        if (tn < nTiles) {
            int rowsN = tileRows(tn);
            stage_tile(x + tn * STAGE_FLOATS, t + tn * STAGE_FLOATS,
                       buf ? sxa0 : sxa1, buf ? sta0 : sta1,
                       tileChunks(rowsN));
        }
        asm volatile("cp.async.commit_group;");
        asm volatile("cp.async.wait_group 1;");
        __syncthreads();                         // stage 'buf' visible to all

        const int rows = tileRows(tile);
        const int fullFloats = tileChunks(rows) << 2;
        const int r = threadIdx.x;
        if (r < rows) {
            const int base = r * C;
            float vx[C], vt[C];
            if (base + C <= fullFloats) {
                // common case: whole row staged; 56B row @ 8B-aligned base
                const float2* px = (const float2*)(sx[buf] + base);
                const float2* pt = (const float2*)(st[buf] + base);
#pragma unroll
                for (int k = 0; k < 7; k++) {
                    float2 a = px[k]; vx[2 * k] = a.x; vx[2 * k + 1] = a.y;
                    float2 b = pt[k]; vt[2 * k] = b.x; vt[2 * k + 1] = b.y;
                }
            } else {
                // last partial chunk of an odd-rows tail tile
                const float* gxr = x + tile * STAGE_FLOATS;
                const float* gtr = t + tile * STAGE_FLOATS;
#pragma unroll
                for (int c = 0; c < C; c++) {
                    int idx = base + c;
                    if (idx < fullFloats) { vx[c] = sx[buf][idx]; vt[c] = st[buf][idx]; }
                    else                  { vx[c] = __ldg(&gxr[idx]); vt[c] = __ldg(&gtr[idx]); }
                }
            }

            // per-row target sums for groups 1..3 (group 0 always kept)
            float g1 = 0.0f, g2 = 0.0f, g3 = 0.0f;
#pragma unroll
            for (int c = 0; c < C; c++) {
                int g = gl[c];
                float tv = vt[c];
                g1 += (g == 1) ? tv : 0.0f;
                g2 += (g == 2) ? tv : 0.0f;
                g3 += (g == 3) ? tv : 0.0f;
            }
            const float m1 = (g1 > 0.0f) ? 1.0f : 0.0f;
            const float m2 = (g2 > 0.0f) ? 1.0f : 0.0f;
            const float m3 = (g3 > 0.0f) ? 1.0f : 0.0f;

#pragma unroll
            for (int c = 0; c < C; c++) {
                float xv = vx[c];
                float tv = vt[c];
                float ax = fabsf(xv);
                // log1p(exp(-|x|)) via fast intrinsics: when 1+e rounds away
                // the term (|x|>16.6) the dropped part is <1e-7 — negligible
                // at 1e-3 rel tolerance on the mean.
                float l = __logf(1.0f + __expf(-ax));
                float bce = fmaxf(xv, 0.0f) - xv * tv + l;
                int g = gl[c];
                float m = (g == 0) ? 1.0f
                        : (g == 1) ? m1
                        : (g == 2) ? m2
                        : m3;
                s += bce * m;
            }
        }
        __syncthreads();   // all reads of 'buf' done before it is restaged
        buf ^= 1;
    }

    // block reduction
#pragma unroll
    for (int off = 16; off > 0; off >>= 1)
        s += __shfl_down_sync(0xFFFFFFFFu, s, off);

    const int lane = threadIdx.x & 31;
    const int wid  = threadIdx.x >> 5;
    if (lane == 0) warp_sums[wid] = s;
    __syncthreads();

    if (threadIdx.x == 0) {
        float v = 0.0f;
#pragma unroll
        for (int w = 0; w < THREADS / 32; w++) v += warp_sums[w];
        atomicAdd(&g_acc, (double)v);

        __threadfence();
        unsigned prev = atomicAdd(&g_count, 1u);
        if (prev == gridDim.x - 1) {
            // last block: publish result, reset state for next graph replay
            __threadfence();
            out[0] = (float)(g_acc * inv_n);
            g_acc = 0.0;
            g_count = 0u;
        }
    }
}

extern "C" void kernel_launch(void* const* d_in, const int* in_sizes, int n_in,
                              void* d_out, int out_size)
{
    const float* x      = (const float*)d_in[0];
    const float* t      = (const float*)d_in[1];
    const int*   groups = (const int*)d_in[2];
    float* out = (float*)d_out;

    const long long total = in_sizes[0];   // B * C
    const int B = (int)(total / C);

    const double inv_n = 1.0 / (double)((long long)B * C);

    bce_fused_kernel<<<GRID_CTAS, THREADS>>>(x, t, groups, out, B, inv_n);
}